// round 2
// baseline (speedup 1.0000x reference)
#include <cuda_runtime.h>
#include <math.h>

#define BB 32
#define DD 1024
#define TXX 4096
#define WIN 4
#define NW 8          // 2*WINDOW
#define KSPLIT1 8     // K=1024 -> chunks of 128
#define KSPLIT3 16    // K=2048 -> chunks of 128

// Scratch (device globals; no allocation allowed)
__device__ float g_target[BB * DD];             // input @ W_in^T
__device__ float g_pt_part[KSPLIT1][BB][512];   // split-K partials of input @ W_p1^T (pre-tanh)
__device__ float g_weighted[BB * DD];           // attn-weighted context
__device__ float g_h[BB * DD];                  // pre-tanh output accumulator

// ---------------------------------------------------------------------------
// Zero the atomic accumulators (g_target, g_h). g_pt_part is fully overwritten.
__global__ void k_zero() {
    int i = blockIdx.x * blockDim.x + threadIdx.x;
    if (i < BB * DD) { g_target[i] = 0.f; g_h[i] = 0.f; }
}

// ---------------------------------------------------------------------------
// Core tile: out[32, j0:j0+64] += X[:, kx0:kx0+kchunk] * W[j, kw0:kw0+kchunk]^T
// blockDim = 128. Thread tile 4(b) x 4(j): 2x LDS.128 per 16 FMA -> FMA-bound.
template <bool ATOMIC>
__device__ __forceinline__ void gemm_tile(
    const float* __restrict__ X, int xstride, int kx0,
    const float* __restrict__ W, int wstride, int kw0,
    int kchunk,
    float* __restrict__ out, int ostride, int j0)
{
    __shared__ float Xs[32][36];   // [k][b], pad 36 (144B rows: 16B aligned)
    __shared__ float Ws[32][68];   // [k][j], pad 68 (272B rows: 16B aligned)

    const int t  = threadIdx.x;
    const int tb = t & 7;          // 8 groups  -> b0 = tb*4
    const int tj = t >> 3;         // 16 groups -> j0 local = tj*4

    float acc[4][4];
#pragma unroll
    for (int i = 0; i < 4; i++)
#pragma unroll
        for (int j = 0; j < 4; j++) acc[i][j] = 0.f;

    for (int kt = 0; kt < kchunk; kt += 32) {
        // Load X tile: 32(b) x 32(k), coalesced along k, store transposed [k][b]
#pragma unroll
        for (int i = t; i < 32 * 32; i += 128) {
            int b = i >> 5, k = i & 31;
            Xs[k][b] = X[b * xstride + kx0 + kt + k];
        }
        // Load W tile: 64(j) x 32(k), coalesced along k, store transposed [k][j]
#pragma unroll
        for (int i = t; i < 64 * 32; i += 128) {
            int j = i >> 5, k = i & 31;
            Ws[k][j] = W[(size_t)(j0 + j) * wstride + kw0 + kt + k];
        }
        __syncthreads();

#pragma unroll
        for (int k = 0; k < 32; k++) {
            float4 x = *(const float4*)&Xs[k][tb * 4];
            float4 w = *(const float4*)&Ws[k][tj * 4];
            acc[0][0] += x.x * w.x; acc[0][1] += x.x * w.y; acc[0][2] += x.x * w.z; acc[0][3] += x.x * w.w;
            acc[1][0] += x.y * w.x; acc[1][1] += x.y * w.y; acc[1][2] += x.y * w.z; acc[1][3] += x.y * w.w;
            acc[2][0] += x.z * w.x; acc[2][1] += x.z * w.y; acc[2][2] += x.z * w.z; acc[2][3] += x.z * w.w;
            acc[3][0] += x.w * w.x; acc[3][1] += x.w * w.y; acc[3][2] += x.w * w.z; acc[3][3] += x.w * w.w;
        }
        __syncthreads();
    }

#pragma unroll
    for (int i = 0; i < 4; i++) {
#pragma unroll
        for (int jj = 0; jj < 4; jj++) {
            float* p = &out[(tb * 4 + i) * ostride + j0 + tj * 4 + jj];
            if (ATOMIC) atomicAdd(p, acc[i][jj]);
            else        *p = acc[i][jj];
        }
    }
}

// K1: target = input @ W_in^T (atomic split-K)  AND  pt partials = input @ W_p1^T
// grid (24, KSPLIT1): nb<16 -> target columns, nb>=16 -> pt columns
__global__ void k_gemm1(const float* __restrict__ input,
                        const float* __restrict__ W_in,
                        const float* __restrict__ W_p1) {
    int nb = blockIdx.x;
    int kc = blockIdx.y;
    int kc0 = kc * (DD / KSPLIT1);
    if (nb < 16) {
        gemm_tile<true>(input, DD, kc0, W_in, DD, kc0, DD / KSPLIT1,
                        g_target, DD, nb * 64);
    } else {
        // deterministic: each (kc, column-range) owns a distinct partial slab
        gemm_tile<false>(input, DD, kc0, W_p1, DD, kc0, DD / KSPLIT1,
                         &g_pt_part[kc][0][0], 512, (nb - 16) * 64);
    }
}

// K3: h = cat(weighted, input) @ W_out^T (atomic split-K). grid (16, KSPLIT3)
__global__ void k_gemm3(const float* __restrict__ input,
                        const float* __restrict__ W_out) {
    int kg0 = blockIdx.y * (2 * DD / KSPLIT3);       // global k offset in [0, 2048)
    const float* X = (kg0 < DD) ? g_weighted : input;
    int kx0 = kg0 & (DD - 1);
    gemm_tile<true>(X, DD, kx0, W_out, 2 * DD, kg0, 2 * DD / KSPLIT3,
                    g_h, DD, blockIdx.x * 64);
}

// ---------------------------------------------------------------------------
// K2: per-batch predictive position + gather + scores + softmax + weighted sum
// grid = 32 (one block per batch row), blockDim = 256 (8 warps)
__global__ void k_attn(const float* __restrict__ context,
                       const float* __restrict__ W_p2,
                       float* __restrict__ out_attn) {
    const int b = blockIdx.x;
    const int t = threadIdx.x;
    const int warp = t >> 5, lane = t & 31;

    __shared__ float s_cw[NW][DD];     // gathered context window (32KB)
    __shared__ float s_t[DD];          // target row
    __shared__ float s_red[8];
    __shared__ float s_scores[NW];
    __shared__ float s_attn[NW];
    __shared__ int   s_idx[NW];

    // Phase 0: s = sum_i tanh(sum_split pt_part) * W_p2[i]   (deterministic)
    float local = 0.f;
    for (int i = t; i < 512; i += 256) {
        float v = 0.f;
#pragma unroll
        for (int p = 0; p < KSPLIT1; p++) v += g_pt_part[p][b][i];
        local += tanhf(v) * W_p2[i];
    }
#pragma unroll
    for (int o = 16; o; o >>= 1) local += __shfl_xor_sync(0xffffffffu, local, o);
    if (lane == 0) s_red[warp] = local;
    __syncthreads();

    if (t == 0) {
        float s = 0.f;
#pragma unroll
        for (int w = 0; w < 8; w++) s += s_red[w];
        float pt2 = (float)TXX * (1.f / (1.f + expf(-s)));
        int bl = (int)truncf(pt2 - (float)WIN);     // trunc toward zero, like jnp.trunc+int32
#pragma unroll
        for (int w = 0; w < NW; w++) {
            int id = bl + w;
            id = id < 0 ? 0 : (id > TXX - 1 ? TXX - 1 : id);
            s_idx[w] = id;
        }
    }
    __syncthreads();

    // Phase 1: load target row + gather 8 context rows into smem (float4)
    {
        const float4* tg = (const float4*)&g_target[b * DD];
        float4* st = (float4*)s_t;
        for (int i = t; i < DD / 4; i += 256) st[i] = tg[i];
    }
    {
        const float4* crow =
            (const float4*)&context[((size_t)b * TXX + s_idx[warp]) * DD];
        float4* dst = (float4*)&s_cw[warp][0];
        for (int i = lane; i < DD / 4; i += 32) dst[i] = crow[i];
    }
    __syncthreads();

    // Phase 2: scores[w] = dot(cw[w], target)  (warp w)
    {
        const float4* c4 = (const float4*)&s_cw[warp][0];
        const float4* t4 = (const float4*)s_t;
        float p = 0.f;
        for (int i = lane; i < DD / 4; i += 32) {
            float4 c = c4[i], x = t4[i];
            p += c.x * x.x + c.y * x.y + c.z * x.z + c.w * x.w;
        }
#pragma unroll
        for (int o = 16; o; o >>= 1) p += __shfl_xor_sync(0xffffffffu, p, o);
        if (lane == 0) s_scores[warp] = p;
    }
    __syncthreads();

    // Phase 3: softmax over 8 (single thread; write attn output)
    if (t == 0) {
        float m = -1e30f;
#pragma unroll
        for (int w = 0; w < NW; w++) m = fmaxf(m, s_scores[w]);
        float e[NW], sum = 0.f;
#pragma unroll
        for (int w = 0; w < NW; w++) { e[w] = expf(s_scores[w] - m); sum += e[w]; }
        float inv = 1.f / sum;
#pragma unroll
        for (int w = 0; w < NW; w++) {
            float a = e[w] * inv;
            s_attn[w] = a;
            out_attn[b * NW + w] = a;
        }
    }
    __syncthreads();

    // Phase 4: weighted[b,:] = sum_w attn[w] * cw[w,:]
    {
        float4* wout = (float4*)&g_weighted[b * DD];
        for (int i = t; i < DD / 4; i += 256) {
            float4 acc = make_float4(0.f, 0.f, 0.f, 0.f);
#pragma unroll
            for (int w = 0; w < NW; w++) {
                float a = s_attn[w];
                float4 c = ((const float4*)&s_cw[w][0])[i];
                acc.x += a * c.x; acc.y += a * c.y; acc.z += a * c.z; acc.w += a * c.w;
            }
            wout[i] = acc;
        }
    }
}

// K4: h_tilde = tanh(g_h) -> d_out[0:32768]
__global__ void k_tanh(float* __restrict__ out) {
    int i = blockIdx.x * blockDim.x + threadIdx.x;
    if (i < BB * DD) out[i] = tanhf(g_h[i]);
}

// ---------------------------------------------------------------------------
extern "C" void kernel_launch(void* const* d_in, const int* in_sizes, int n_in,
                              void* d_out, int out_size) {
    const float *input = 0, *context = 0, *W_in = 0, *W_out = 0, *W_p1 = 0, *W_p2 = 0;
    for (int i = 0; i < n_in; i++) {
        switch (in_sizes[i]) {
            case BB * DD:            input   = (const float*)d_in[i]; break; // 32768
            case BB * TXX * DD:      context = (const float*)d_in[i]; break; // 134217728
            case DD * DD:            W_in    = (const float*)d_in[i]; break; // 1048576
            case DD * 2 * DD:        W_out   = (const float*)d_in[i]; break; // 2097152
            case 512 * DD:           W_p1    = (const float*)d_in[i]; break; // 524288
            case 512:                W_p2    = (const float*)d_in[i]; break;
        }
    }
    float* out = (float*)d_out;

    k_zero<<<(BB * DD + 255) / 256, 256>>>();
    k_gemm1<<<dim3(24, KSPLIT1), 128>>>(input, W_in, W_p1);
    k_attn<<<BB, 256>>>(context, W_p2, out + BB * DD);
    k_gemm3<<<dim3(16, KSPLIT3), 128>>>(input, W_out);
    k_tanh<<<(BB * DD + 255) / 256, 256>>>(out);
}

// round 3
// speedup vs baseline: 1.3835x; 1.3835x over previous
#include <cuda_runtime.h>
#include <math.h>

#define BB 32
#define DD 1024
#define TXX 4096
#define WIN 4
#define NW 8            // 2*WINDOW
#define KC 64           // k-chunk per block
#define KS1 16          // gemm1: K=1024 -> 16 chunks of 64
#define KS3 32          // gemm3: K=2048 -> 32 chunks of 64

// Scratch (device globals; allocation is forbidden). All split-K partials are
// written to private slabs and reduced in fixed order -> fully deterministic.
__device__ float g_t_part[KS1][BB][DD];    // input @ W_in^T partials   (2 MB)
__device__ float g_pt_part[KS1][BB][512];  // input @ W_p1^T partials   (1 MB)
__device__ float g_h_part[KS3][BB][DD];    // cat @ W_out^T partials    (4 MB)
__device__ float g_weighted[BB * DD];      // attn-weighted context

// ---------------------------------------------------------------------------
// One-stage tile: out[32, j0:j0+64] = X[:, kx0:kx0+64] * W[j, kw0:kw0+64]^T
// blockDim = 128. Per-thread 4(b) x 4(j) register tile, inner loop is
// 2x LDS.128 per 16 FFMA with 16 independent accumulators (ILP-bound).
__device__ __forceinline__ void gemm64(
    const float* __restrict__ X, int xstride, int kx0,
    const float* __restrict__ W, int wstride, int kw0,
    float* __restrict__ out, int ostride, int j0)
{
    __shared__ float Xs[KC][36];   // [k][b]
    __shared__ float Ws[KC][68];   // [k][j]

    const int t  = threadIdx.x;
    const int tb = t & 7;          // 8 b-groups  -> rows tb*4..tb*4+3
    const int tj = t >> 3;         // 16 j-groups -> cols tj*4..tj*4+3

    // Load X tile 32b x 64k (coalesced float4 along k), store transposed
    const float4* X4 = (const float4*)X;
#pragma unroll
    for (int i = t; i < 32 * 16; i += 128) {
        int b = i >> 4, kq = i & 15;
        float4 v = X4[(size_t)b * (xstride >> 2) + (kx0 >> 2) + kq];
        Xs[kq * 4 + 0][b] = v.x; Xs[kq * 4 + 1][b] = v.y;
        Xs[kq * 4 + 2][b] = v.z; Xs[kq * 4 + 3][b] = v.w;
    }
    // Load W tile 64j x 64k (coalesced float4 along k), store transposed
    const float4* W4 = (const float4*)W;
#pragma unroll
    for (int i = t; i < 64 * 16; i += 128) {
        int j = i >> 4, kq = i & 15;
        float4 v = W4[(size_t)(j0 + j) * (wstride >> 2) + (kw0 >> 2) + kq];
        Ws[kq * 4 + 0][j] = v.x; Ws[kq * 4 + 1][j] = v.y;
        Ws[kq * 4 + 2][j] = v.z; Ws[kq * 4 + 3][j] = v.w;
    }
    __syncthreads();

    float acc[4][4];
#pragma unroll
    for (int i = 0; i < 4; i++)
#pragma unroll
        for (int j = 0; j < 4; j++) acc[i][j] = 0.f;

#pragma unroll 16
    for (int k = 0; k < KC; k++) {
        float4 x = *(const float4*)&Xs[k][tb * 4];
        float4 w = *(const float4*)&Ws[k][tj * 4];
        acc[0][0] += x.x * w.x; acc[0][1] += x.x * w.y; acc[0][2] += x.x * w.z; acc[0][3] += x.x * w.w;
        acc[1][0] += x.y * w.x; acc[1][1] += x.y * w.y; acc[1][2] += x.y * w.z; acc[1][3] += x.y * w.w;
        acc[2][0] += x.z * w.x; acc[2][1] += x.z * w.y; acc[2][2] += x.z * w.z; acc[2][3] += x.z * w.w;
        acc[3][0] += x.w * w.x; acc[3][1] += x.w * w.y; acc[3][2] += x.w * w.z; acc[3][3] += x.w * w.w;
    }

    // Write partial tile (float4 per row-quad, no atomics)
#pragma unroll
    for (int i = 0; i < 4; i++) {
        float4 v = make_float4(acc[i][0], acc[i][1], acc[i][2], acc[i][3]);
        *(float4*)&out[(size_t)(tb * 4 + i) * ostride + j0 + tj * 4] = v;
    }
}

// K1: partials of target = input @ W_in^T and pt = input @ W_p1^T
// grid (24, KS1): nb<16 -> W_in j-tiles, nb>=16 -> W_p1 j-tiles
__global__ void k_gemm1(const float* __restrict__ input,
                        const float* __restrict__ W_in,
                        const float* __restrict__ W_p1) {
    int nb = blockIdx.x, kc = blockIdx.y;
    int k0 = kc * KC;
    if (nb < 16)
        gemm64(input, DD, k0, W_in, DD, k0, &g_t_part[kc][0][0], DD, nb * 64);
    else
        gemm64(input, DD, k0, W_p1, DD, k0, &g_pt_part[kc][0][0], 512, (nb - 16) * 64);
}

// K3: partials of h = cat(weighted, input) @ W_out^T. grid (16, KS3)
__global__ void k_gemm3(const float* __restrict__ input,
                        const float* __restrict__ W_out) {
    int kg0 = blockIdx.y * KC;                 // [0, 2048)
    const float* X = (kg0 < DD) ? g_weighted : input;
    gemm64(X, DD, kg0 & (DD - 1), W_out, 2 * DD, kg0,
           &g_h_part[blockIdx.y][0][0], DD, blockIdx.x * 64);
}

// ---------------------------------------------------------------------------
// K2: per-batch pt reduction + index + gather + scores + softmax + weighted
// grid = 32 blocks (one per batch row), blockDim = 256 (8 warps)
__global__ void k_attn(const float* __restrict__ context,
                       const float* __restrict__ W_p2,
                       float* __restrict__ out_attn) {
    const int b = blockIdx.x;
    const int t = threadIdx.x;
    const int warp = t >> 5, lane = t & 31;

    __shared__ float s_cw[NW][DD];     // gathered context window (32KB)
    __shared__ float s_t[DD];          // target row (reduced from partials)
    __shared__ float s_red[8];
    __shared__ float s_scores[NW];
    __shared__ float s_attn[NW];
    __shared__ int   s_idx[NW];

    // Phase 0a: reduce target partials into smem (fixed order)
    for (int i = t; i < DD; i += 256) {
        float v = 0.f;
#pragma unroll
        for (int p = 0; p < KS1; p++) v += g_t_part[p][b][i];
        s_t[i] = v;
    }

    // Phase 0b: s = sum_i tanh(sum_p pt_part) * W_p2[i]   (deterministic)
    float local = 0.f;
    for (int i = t; i < 512; i += 256) {
        float v = 0.f;
#pragma unroll
        for (int p = 0; p < KS1; p++) v += g_pt_part[p][b][i];
        local += tanhf(v) * W_p2[i];
    }
#pragma unroll
    for (int o = 16; o; o >>= 1) local += __shfl_xor_sync(0xffffffffu, local, o);
    if (lane == 0) s_red[warp] = local;
    __syncthreads();

    if (t == 0) {
        float s = 0.f;
#pragma unroll
        for (int w = 0; w < 8; w++) s += s_red[w];
        float pt2 = (float)TXX * (1.f / (1.f + expf(-s)));
        int bl = (int)truncf(pt2 - (float)WIN);   // trunc toward zero == jnp.trunc->int32
#pragma unroll
        for (int w = 0; w < NW; w++) {
            int id = bl + w;
            id = id < 0 ? 0 : (id > TXX - 1 ? TXX - 1 : id);
            s_idx[w] = id;
        }
    }
    __syncthreads();

    // Phase 1: gather 8 context rows into smem (warp w -> row w, float4)
    {
        const float4* crow =
            (const float4*)&context[((size_t)b * TXX + s_idx[warp]) * DD];
        float4* dst = (float4*)&s_cw[warp][0];
        for (int i = lane; i < DD / 4; i += 32) dst[i] = crow[i];
    }
    __syncthreads();

    // Phase 2: scores[w] = dot(cw[w], target)
    {
        const float4* c4 = (const float4*)&s_cw[warp][0];
        const float4* t4 = (const float4*)s_t;
        float p = 0.f;
        for (int i = lane; i < DD / 4; i += 32) {
            float4 c = c4[i], x = t4[i];
            p += c.x * x.x + c.y * x.y + c.z * x.z + c.w * x.w;
        }
#pragma unroll
        for (int o = 16; o; o >>= 1) p += __shfl_xor_sync(0xffffffffu, p, o);
        if (lane == 0) s_scores[warp] = p;
    }
    __syncthreads();

    // Phase 3: softmax over 8
    if (t == 0) {
        float m = -1e30f;
#pragma unroll
        for (int w = 0; w < NW; w++) m = fmaxf(m, s_scores[w]);
        float e[NW], sum = 0.f;
#pragma unroll
        for (int w = 0; w < NW; w++) { e[w] = expf(s_scores[w] - m); sum += e[w]; }
        float inv = 1.f / sum;
#pragma unroll
        for (int w = 0; w < NW; w++) {
            float a = e[w] * inv;
            s_attn[w] = a;
            out_attn[b * NW + w] = a;
        }
    }
    __syncthreads();

    // Phase 4: weighted[b,:] = sum_w attn[w] * cw[w,:]
    {
        float4* wout = (float4*)&g_weighted[b * DD];
        for (int i = t; i < DD / 4; i += 256) {
            float4 acc = make_float4(0.f, 0.f, 0.f, 0.f);
#pragma unroll
            for (int w = 0; w < NW; w++) {
                float a = s_attn[w];
                float4 c = ((const float4*)&s_cw[w][0])[i];
                acc.x += a * c.x; acc.y += a * c.y; acc.z += a * c.z; acc.w += a * c.w;
            }
            wout[i] = acc;
        }
    }
}

// K4: h_tilde = tanh(sum_p h_part) -> d_out[0:32768]  (fixed-order reduce)
__global__ void k_out(float* __restrict__ out) {
    int i = blockIdx.x * blockDim.x + threadIdx.x;   // 32768 threads
    float v = 0.f;
#pragma unroll
    for (int p = 0; p < KS3; p++) v += g_h_part[p][0][i];
    out[i] = tanhf(v);
}

// ---------------------------------------------------------------------------
extern "C" void kernel_launch(void* const* d_in, const int* in_sizes, int n_in,
                              void* d_out, int out_size) {
    const float *input = 0, *context = 0, *W_in = 0, *W_out = 0, *W_p1 = 0, *W_p2 = 0;
    for (int i = 0; i < n_in; i++) {
        switch (in_sizes[i]) {
            case BB * DD:       input   = (const float*)d_in[i]; break; // 32768
            case BB * TXX * DD: context = (const float*)d_in[i]; break; // 134217728
            case DD * DD:       W_in    = (const float*)d_in[i]; break; // 1048576
            case DD * 2 * DD:   W_out   = (const float*)d_in[i]; break; // 2097152
            case 512 * DD:      W_p1    = (const float*)d_in[i]; break; // 524288
            case 512:           W_p2    = (const float*)d_in[i]; break;
        }
    }
    float* out = (float*)d_out;

    k_gemm1<<<dim3(24, KS1), 128>>>(input, W_in, W_p1);
    k_attn<<<BB, 256>>>(context, W_p2, out + BB * DD);
    k_gemm3<<<dim3(16, KS3), 128>>>(input, W_out);
    k_out<<<BB * DD / 256, 256>>>(out);
}

// round 6
// speedup vs baseline: 1.4064x; 1.0165x over previous
#include <cuda_runtime.h>
#include <math.h>

#define BB 32
#define DD 1024
#define TXX 4096
#define WIN 4
#define NW 8            // 2*WINDOW
#define KC 64           // k-chunk per gemm block
#define KS1 16          // gemm1: K=1024 -> 16 chunks
#define KS3 32          // gemm3: K=2048 -> 32 chunks (16 weighted + 16 input)

// Scratch (device globals; allocation forbidden). Split-K partials in private
// slabs, reduced in fixed order -> deterministic.
__device__ float  g_t_part[KS1][BB][DD];    // input @ W_in^T partials
__device__ float  g_pt_part[KS1][BB][512];  // input @ W_p1^T partials
__device__ float  g_h_part[KS3][BB][DD];    // cat @ W_out^T partials (4MB)
__device__ float  g_weighted[BB * DD];      // attn-weighted context
__device__ float4 g_h2[4][BB * DD / 4];     // first-stage h reduction (4 x 8192 float4 = 512KB)

// ---------------------------------------------------------------------------
// One-stage tile: out[32, j0:j0+64] = X[:, kx0:+64] * W[j, kw0:+64]^T
// blockDim = 128, per-thread 4(b) x 4(j) register tile.
__device__ __forceinline__ void gemm64(
    const float* __restrict__ X, int xstride, int kx0,
    const float* __restrict__ W, int wstride, int kw0,
    float* __restrict__ out, int ostride, int j0)
{
    __shared__ float Xs[KC][36];
    __shared__ float Ws[KC][68];

    const int t  = threadIdx.x;
    const int tb = t & 7;
    const int tj = t >> 3;

    const float4* X4 = (const float4*)X;
#pragma unroll
    for (int i = t; i < 32 * 16; i += 128) {
        int b = i >> 4, kq = i & 15;
        float4 v = X4[(size_t)b * (xstride >> 2) + (kx0 >> 2) + kq];
        Xs[kq * 4 + 0][b] = v.x; Xs[kq * 4 + 1][b] = v.y;
        Xs[kq * 4 + 2][b] = v.z; Xs[kq * 4 + 3][b] = v.w;
    }
    const float4* W4 = (const float4*)W;
#pragma unroll
    for (int i = t; i < 64 * 16; i += 128) {
        int j = i >> 4, kq = i & 15;
        float4 v = W4[(size_t)(j0 + j) * (wstride >> 2) + (kw0 >> 2) + kq];
        Ws[kq * 4 + 0][j] = v.x; Ws[kq * 4 + 1][j] = v.y;
        Ws[kq * 4 + 2][j] = v.z; Ws[kq * 4 + 3][j] = v.w;
    }
    __syncthreads();

    float acc[4][4];
#pragma unroll
    for (int i = 0; i < 4; i++)
#pragma unroll
        for (int j = 0; j < 4; j++) acc[i][j] = 0.f;

#pragma unroll 16
    for (int k = 0; k < KC; k++) {
        float4 x = *(const float4*)&Xs[k][tb * 4];
        float4 w = *(const float4*)&Ws[k][tj * 4];
        acc[0][0] += x.x * w.x; acc[0][1] += x.x * w.y; acc[0][2] += x.x * w.z; acc[0][3] += x.x * w.w;
        acc[1][0] += x.y * w.x; acc[1][1] += x.y * w.y; acc[1][2] += x.y * w.z; acc[1][3] += x.y * w.w;
        acc[2][0] += x.z * w.x; acc[2][1] += x.z * w.y; acc[2][2] += x.z * w.z; acc[2][3] += x.z * w.w;
        acc[3][0] += x.w * w.x; acc[3][1] += x.w * w.y; acc[3][2] += x.w * w.z; acc[3][3] += x.w * w.w;
    }

#pragma unroll
    for (int i = 0; i < 4; i++) {
        float4 v = make_float4(acc[i][0], acc[i][1], acc[i][2], acc[i][3]);
        *(float4*)&out[(size_t)(tb * 4 + i) * ostride + j0 + tj * 4] = v;
    }
}

// K_front: everything that depends only on `input`:
//   roles [0,256):   W_in   16 j-tiles x 16 k-chunks -> g_t_part
//   roles [256,384): W_p1    8 j-tiles x 16 k-chunks -> g_pt_part
//   roles [384,640): W_out input-half (k in [1024,2048)) 16x16 -> g_h_part[16+kt]
__global__ void k_front(const float* __restrict__ input,
                        const float* __restrict__ W_in,
                        const float* __restrict__ W_p1,
                        const float* __restrict__ W_out) {
    int r = blockIdx.x;
    if (r < 256) {
        int jt = r & 15, kt = r >> 4;
        gemm64(input, DD, kt * KC, W_in, DD, kt * KC,
               &g_t_part[kt][0][0], DD, jt * 64);
    } else if (r < 384) {
        int rr = r - 256, jt = rr & 7, kt = rr >> 3;
        gemm64(input, DD, kt * KC, W_p1, DD, kt * KC,
               &g_pt_part[kt][0][0], 512, jt * 64);
    } else {
        int rr = r - 384, jt = rr & 15, kt = rr >> 4;
        gemm64(input, DD, kt * KC, W_out, 2 * DD, DD + kt * KC,
               &g_h_part[16 + kt][0][0], DD, jt * 64);
    }
}

// K_gemm3a: weighted-half of h (k in [0,1024)). grid (16 j, 16 k)
__global__ void k_gemm3a(const float* __restrict__ W_out) {
    int jt = blockIdx.x, kt = blockIdx.y;
    gemm64(g_weighted, DD, kt * KC, W_out, 2 * DD, kt * KC,
           &g_h_part[kt][0][0], DD, jt * 64);
}

// ---------------------------------------------------------------------------
// K_attn: per-batch pt reduce + index + gather + scores + softmax + weighted
// grid = 32 blocks, blockDim = 512 (16 warps; 2 warps per window row)
__global__ void k_attn(const float* __restrict__ context,
                       const float* __restrict__ W_p2,
                       float* __restrict__ out_attn) {
    const int b = blockIdx.x;
    const int t = threadIdx.x;
    const int warp = t >> 5, lane = t & 31;

    __shared__ float s_cw[NW][DD];     // 32KB
    __shared__ float s_t[DD];          // 4KB
    __shared__ float s_red[16];
    __shared__ float s_part[16];
    __shared__ float s_attn[NW];
    __shared__ int   s_idx[NW];

    // Phase 0a: reduce target partials into smem (float4, fixed order)
    if (t < 256) {
        float4 v = make_float4(0.f, 0.f, 0.f, 0.f);
#pragma unroll
        for (int p = 0; p < KS1; p++) {
            float4 u = ((const float4*)&g_t_part[p][b][0])[t];
            v.x += u.x; v.y += u.y; v.z += u.z; v.w += u.w;
        }
        ((float4*)s_t)[t] = v;
    }

    // Phase 0b: s = sum_i tanh(sum_p pt_part_i) * W_p2_i   (float4, fixed order)
    float local = 0.f;
    if (t < 128) {
        float4 v = make_float4(0.f, 0.f, 0.f, 0.f);
#pragma unroll
        for (int p = 0; p < KS1; p++) {
            float4 u = ((const float4*)&g_pt_part[p][b][0])[t];
            v.x += u.x; v.y += u.y; v.z += u.z; v.w += u.w;
        }
        float4 w = ((const float4*)W_p2)[t];
        local = tanhf(v.x) * w.x + tanhf(v.y) * w.y
              + tanhf(v.z) * w.z + tanhf(v.w) * w.w;
    }
#pragma unroll
    for (int o = 16; o; o >>= 1) local += __shfl_xor_sync(0xffffffffu, local, o);
    if (lane == 0) s_red[warp] = local;
    __syncthreads();

    if (t == 0) {
        float s = 0.f;
#pragma unroll
        for (int w = 0; w < 16; w++) s += s_red[w];
        float pt2 = (float)TXX * (1.f / (1.f + expf(-s)));
        int bl = (int)truncf(pt2 - (float)WIN);   // trunc == jnp.trunc -> int32
#pragma unroll
        for (int w = 0; w < NW; w++) {
            int id = bl + w;
            id = id < 0 ? 0 : (id > TXX - 1 ? TXX - 1 : id);
            s_idx[w] = id;
        }
    }
    __syncthreads();

    // Phase 1: gather 8 context rows (2 warps per row, float4)
    {
        const int row  = warp >> 1;
        const int half = warp & 1;
        const float4* crow =
            (const float4*)&context[((size_t)b * TXX + s_idx[row]) * DD];
        float4* dst = (float4*)&s_cw[row][0];
#pragma unroll
        for (int q = 0; q < 4; q++) {
            int i = half * 128 + q * 32 + lane;
            dst[i] = crow[i];
        }
    }
    __syncthreads();

    // Phase 2: scores (2 warps per row, fixed-order combine)
    {
        const int row  = warp >> 1;
        const int half = warp & 1;
        const float4* c4 = (const float4*)&s_cw[row][0];
        const float4* t4 = (const float4*)s_t;
        float p = 0.f;
#pragma unroll
        for (int q = 0; q < 4; q++) {
            int i = half * 128 + q * 32 + lane;
            float4 c = c4[i], x = t4[i];
            p += c.x * x.x + c.y * x.y + c.z * x.z + c.w * x.w;
        }
#pragma unroll
        for (int o = 16; o; o >>= 1) p += __shfl_xor_sync(0xffffffffu, p, o);
        if (lane == 0) s_part[warp] = p;
    }
    __syncthreads();

    // Phase 3: softmax over 8
    if (t == 0) {
        float sc[NW];
#pragma unroll
        for (int w = 0; w < NW; w++) sc[w] = s_part[2 * w] + s_part[2 * w + 1];
        float m = -1e30f;
#pragma unroll
        for (int w = 0; w < NW; w++) m = fmaxf(m, sc[w]);
        float e[NW], sum = 0.f;
#pragma unroll
        for (int w = 0; w < NW; w++) { e[w] = expf(sc[w] - m); sum += e[w]; }
        float inv = 1.f / sum;
#pragma unroll
        for (int w = 0; w < NW; w++) {
            float a = e[w] * inv;
            s_attn[w] = a;
            out_attn[b * NW + w] = a;
        }
    }
    __syncthreads();

    // Phase 4: weighted[b,:] = sum_w attn[w] * cw[w,:]
    if (t < 256) {
        float4 acc = make_float4(0.f, 0.f, 0.f, 0.f);
#pragma unroll
        for (int w = 0; w < NW; w++) {
            float a = s_attn[w];
            float4 c = ((const float4*)&s_cw[w][0])[t];
            acc.x += a * c.x; acc.y += a * c.y; acc.z += a * c.z; acc.w += a * c.w;
        }
        ((float4*)&g_weighted[b * DD])[t] = acc;
    }
}

// K_out1: first-stage h reduction. 32768 threads: pg in [0,4), q float4 idx in [0,8192).
__global__ void k_out1() {
    int i = blockIdx.x * 256 + threadIdx.x;     // [0, 32768)
    int pg = i >> 13, q = i & 8191;
    float4 a = make_float4(0.f, 0.f, 0.f, 0.f);
#pragma unroll
    for (int p = 0; p < 8; p++) {
        float4 v = ((const float4*)&g_h_part[pg * 8 + p][0][0])[q];
        a.x += v.x; a.y += v.y; a.z += v.z; a.w += v.w;
    }
    g_h2[pg][q] = a;
}

// K_out2: final sum + tanh -> d_out[0:32768]
__global__ void k_out2(float* __restrict__ out) {
    int q = blockIdx.x * 256 + threadIdx.x;     // [0, 8192)
    float4 a0 = g_h2[0][q], a1 = g_h2[1][q], a2 = g_h2[2][q], a3 = g_h2[3][q];
    float4 r;
    r.x = tanhf(a0.x + a1.x + a2.x + a3.x);
    r.y = tanhf(a0.y + a1.y + a2.y + a3.y);
    r.z = tanhf(a0.z + a1.z + a2.z + a3.z);
    r.w = tanhf(a0.w + a1.w + a2.w + a3.w);
    ((float4*)out)[q] = r;
}

// ---------------------------------------------------------------------------
extern "C" void kernel_launch(void* const* d_in, const int* in_sizes, int n_in,
                              void* d_out, int out_size) {
    const float *input = 0, *context = 0, *W_in = 0, *W_out = 0, *W_p1 = 0, *W_p2 = 0;
    for (int i = 0; i < n_in; i++) {
        switch (in_sizes[i]) {
            case BB * DD:       input   = (const float*)d_in[i]; break;
            case BB * TXX * DD: context = (const float*)d_in[i]; break;
            case DD * DD:       W_in    = (const float*)d_in[i]; break;
            case DD * 2 * DD:   W_out   = (const float*)d_in[i]; break;
            case 512 * DD:      W_p1    = (const float*)d_in[i]; break;
            case 512:           W_p2    = (const float*)d_in[i]; break;
        }
    }
    float* out = (float*)d_out;

    k_front<<<640, 128>>>(input, W_in, W_p1, W_out);
    k_attn<<<BB, 512>>>(context, W_p2, out + BB * DD);
    k_gemm3a<<<dim3(16, 16), 128>>>(W_out);
    k_out1<<<128, 256>>>();
    k_out2<<<32, 256>>>(out);
}